// round 8
// baseline (speedup 1.0000x reference)
#include <cuda_runtime.h>
#include <cuda_fp16.h>
#include <cstdint>

#define NB 4
#define NA 4096
#define ND 128

__device__ __half g_Qh[NB * NA * ND];
__device__ __half g_Kh[NB * NA * ND];
__device__ __half g_Vt[NB * ND * NA];   // [b][d][a]
__device__ float  g_H [NB * NA * ND];

// ======================= helpers =======================
__device__ __forceinline__ uint32_t smem_u32(const void* p) {
    uint32_t a;
    asm("{ .reg .u64 t; cvta.to.shared.u64 t, %1; cvt.u32.u64 %0, t; }" : "=r"(a) : "l"(p));
    return a;
}
__device__ __forceinline__ void mma_f16(float c[4],
                                        uint32_t a0, uint32_t a1, uint32_t a2, uint32_t a3,
                                        uint32_t b0, uint32_t b1) {
    asm volatile(
        "mma.sync.aligned.m16n8k16.row.col.f32.f16.f16.f32 "
        "{%0,%1,%2,%3},{%4,%5,%6,%7},{%8,%9},{%0,%1,%2,%3};\n"
        : "+f"(c[0]), "+f"(c[1]), "+f"(c[2]), "+f"(c[3])
        : "r"(a0), "r"(a1), "r"(a2), "r"(a3), "r"(b0), "r"(b1));
}
__device__ __forceinline__ void ldsm_x4(uint32_t& r0, uint32_t& r1, uint32_t& r2, uint32_t& r3,
                                        uint32_t addr) {
    asm volatile("ldmatrix.sync.aligned.m8n8.x4.shared.b16 {%0,%1,%2,%3}, [%4];"
                 : "=r"(r0), "=r"(r1), "=r"(r2), "=r"(r3) : "r"(addr));
}
__device__ __forceinline__ void ldsm_x4_t(uint32_t& r0, uint32_t& r1, uint32_t& r2, uint32_t& r3,
                                          uint32_t addr) {
    asm volatile("ldmatrix.sync.aligned.m8n8.x4.trans.shared.b16 {%0,%1,%2,%3}, [%4];"
                 : "=r"(r0), "=r"(r1), "=r"(r2), "=r"(r3) : "r"(addr));
}
__device__ __forceinline__ void cpa16(uint32_t dst, const void* src) {
    asm volatile("cp.async.cg.shared.global [%0], [%1], 16;" :: "r"(dst), "l"(src) : "memory");
}
#define CP_COMMIT() asm volatile("cp.async.commit_group;" ::: "memory")
#define CP_WAIT1()  asm volatile("cp.async.wait_group 1;" ::: "memory")
#define CP_WAIT2()  asm volatile("cp.async.wait_group 2;" ::: "memory")

__device__ __forceinline__ float ex2f(float x) {
    float y; asm("ex2.approx.ftz.f32 %0, %1;" : "=f"(y) : "f"(x)); return y;
}
__device__ __forceinline__ uint32_t pack_h2(float lo, float hi) {
    __half2 h = __floats2half2_rn(lo, hi);
    return *reinterpret_cast<uint32_t*>(&h);
}
__device__ __forceinline__ float swishf(float v) { return v / (1.f + __expf(-v)); }

// convert a 128x128 fp32 weight W (row-major [k][n]) into smem fp16 [k][n], 272B row stride
__device__ __forceinline__ void cvt_w(char* dst, const float* __restrict__ W, int tid) {
    #pragma unroll
    for (int it = 0; it < 16; it++) {
        const int i = tid + it * 256;
        const int r = i >> 5, c4 = (i & 31) * 4;
        const float4 v = *(const float4*)(W + (size_t)i * 4);
        uint2 u;
        u.x = pack_h2(v.x, v.y);
        u.y = pack_h2(v.z, v.w);
        *(uint2*)(dst + r * 272 + c4 * 2) = u;
    }
}

// ======================= Kernel 1: projections via mma (trans-B) =======================
#define PROJ_SMEM (5 * 34816)

__global__ __launch_bounds__(256, 1)
void proj_kernel(const float* __restrict__ x,
                 const float* __restrict__ Wq,
                 const float* __restrict__ Wk,
                 const float* __restrict__ Wv) {
    extern __shared__ __align__(16) char smem[];
    const uint32_t sb = smem_u32(smem);
    const int tid = threadIdx.x;
    const int w = tid >> 5, lane = tid & 31;
    const int g = lane >> 2, t = lane & 3;
    const int tr_r = lane & 15, tr_c = (lane & 16) >> 1;
    const int row0 = blockIdx.x * 128;
    const int b = row0 >> 12, a0 = row0 & (NA - 1);
    const int qw = w * 16;

    __half* sVst = (__half*)(smem + 139264);

    #pragma unroll 4
    for (int it = 0; it < 16; it++) {
        const int i = tid + it * 256;
        const int r = i >> 5, c4 = (i & 31) * 4;
        const float4 v = *(const float4*)(x + (size_t)(row0 + r) * ND + c4);
        uint2 u;
        u.x = pack_h2(v.x, v.y);
        u.y = pack_h2(v.z, v.w);
        *(uint2*)(smem + r * 272 + c4 * 2) = u;
    }
    cvt_w(smem + 34816,  Wq, tid);
    cvt_w(smem + 69632,  Wk, tid);
    cvt_w(smem + 104448, Wv, tid);
    __syncthreads();

    uint32_t xf[8][4];
    #pragma unroll
    for (int s = 0; s < 8; s++) {
        const char* base = (const char*)smem + (qw + g) * 272 + (16 * s + 2 * t) * 2;
        xf[s][0] = *(const uint32_t*)(base);
        xf[s][1] = *(const uint32_t*)(base + 8 * 272);
        xf[s][2] = *(const uint32_t*)(base + 16);
        xf[s][3] = *(const uint32_t*)(base + 8 * 272 + 16);
    }

    const int gr0 = row0 + qw + g;
    #pragma unroll
    for (int m = 0; m < 3; m++) {
        const uint32_t wb = sb + 34816u * (1 + m);
        float o[16][4];
        #pragma unroll
        for (int nt = 0; nt < 16; nt++) { o[nt][0]=o[nt][1]=o[nt][2]=o[nt][3]=0.f; }
        #pragma unroll
        for (int s = 0; s < 8; s++) {
            #pragma unroll
            for (int p = 0; p < 8; p++) {
                uint32_t b0, b1, b2, b3;
                ldsm_x4_t(b0, b1, b2, b3, wb + (uint32_t)((16 * s + tr_r) * 272 + (p * 16 + tr_c) * 2));
                mma_f16(o[2 * p],     xf[s][0], xf[s][1], xf[s][2], xf[s][3], b0, b1);
                mma_f16(o[2 * p + 1], xf[s][0], xf[s][1], xf[s][2], xf[s][3], b2, b3);
            }
        }
        if (m < 2) {
            __half* dst = (m == 0) ? g_Qh : g_Kh;
            #pragma unroll
            for (int nt = 0; nt < 16; nt++) {
                *(uint32_t*)(dst + (size_t)gr0 * ND + nt * 8 + 2 * t)       = pack_h2(o[nt][0], o[nt][1]);
                *(uint32_t*)(dst + (size_t)(gr0 + 8) * ND + nt * 8 + 2 * t) = pack_h2(o[nt][2], o[nt][3]);
            }
        } else {
            #pragma unroll
            for (int nt = 0; nt < 16; nt++) {
                *(uint32_t*)((char*)sVst + (qw + g) * 272 + (nt * 8 + 2 * t) * 2)     = pack_h2(o[nt][0], o[nt][1]);
                *(uint32_t*)((char*)sVst + (qw + g + 8) * 272 + (nt * 8 + 2 * t) * 2) = pack_h2(o[nt][2], o[nt][3]);
            }
        }
    }
    __syncthreads();
    const int c = tid & 127, dgrp = tid >> 7;
    #pragma unroll 4
    for (int k = 0; k < 64; k++) {
        const int dd = dgrp * 64 + k;
        g_Vt[((size_t)(b * ND + dd)) * NA + a0 + c] = sVst[c * 136 + dd];
    }
}

// ======================= Kernel 2: flash attention (4-stage ring, conn in regs) =======================
#define SM_Q     0
#define STAGE_SZ 35840                 // K 17408 + V 18432
#define SM_ST0   34816
#define ATTN_SMEM (SM_ST0 + 4 * STAGE_SZ)   // 178176

__device__ __forceinline__ void load_stage(uint32_t sb, int stage, int b, int k0, int tid) {
    const uint32_t base = sb + (uint32_t)(SM_ST0 + stage * STAGE_SZ);
    const __half* Kg = g_Kh + ((size_t)(b * NA + k0)) * ND;
    #pragma unroll
    for (int i = tid; i < 1024; i += 256) {
        const int r = i >> 4, c = i & 15;
        cpa16(base + (uint32_t)(r * 272 + c * 16), Kg + r * ND + c * 8);
    }
    const __half* Vg = g_Vt + ((size_t)(b * ND)) * NA + k0;
    #pragma unroll
    for (int i = tid; i < 1024; i += 256) {
        const int r = i >> 3, c = i & 7;
        cpa16(base + (uint32_t)(17408 + r * 144 + c * 16), Vg + (size_t)r * NA + c * 8);
    }
}

__global__ __launch_bounds__(256, 1)
void attn_kernel(const float* __restrict__ conn) {
    extern __shared__ __align__(16) char smem[];
    const uint32_t sb = smem_u32(smem);
    const int tid = threadIdx.x;
    const int w = tid >> 5, lane = tid & 31;
    const int g = lane >> 2, t = lane & 3;
    const int b = blockIdx.y;
    const int q0 = blockIdx.x * 128;
    const int qw = w * 16;
    const int r_l = ((lane & 16) >> 1) + (lane & 7);
    const int c_l = (lane & 8);

    // prologue: Q + stage0 (group0), stage1 (group1), stage2 (group2)
    {
        const __half* Qg = g_Qh + ((size_t)(b * NA + q0)) * ND;
        #pragma unroll
        for (int i = tid; i < 2048; i += 256) {
            const int r = i >> 4, c = i & 15;
            cpa16(sb + (uint32_t)(SM_Q + r * 272 + c * 16), Qg + r * ND + c * 8);
        }
    }
    load_stage(sb, 0, b, 0, tid);
    CP_COMMIT();
    load_stage(sb, 1, b, 64, tid);
    CP_COMMIT();
    load_stage(sb, 2, b, 128, tid);
    CP_COMMIT();

    CP_WAIT2();       // Q + stage0 ready
    __syncthreads();

    uint32_t qf[8][4];
    #pragma unroll
    for (int s = 0; s < 8; s++) {
        const char* base = smem + SM_Q + (qw + g) * 272 + (16 * s + 2 * t) * 2;
        qf[s][0] = *(const uint32_t*)(base);
        qf[s][1] = *(const uint32_t*)(base + 8 * 272);
        qf[s][2] = *(const uint32_t*)(base + 16);
        qf[s][3] = *(const uint32_t*)(base + 8 * 272 + 16);
    }

    float o[16][4];
    #pragma unroll
    for (int nt = 0; nt < 16; nt++) { o[nt][0]=o[nt][1]=o[nt][2]=o[nt][3]=0.f; }
    float l0 = 0.f, l1 = 0.f;

    const float* connR0 = conn + ((size_t)(b * NA + q0 + qw + g)) * NA + 2 * t;
    const float* connR1 = connR0 + (size_t)8 * NA;
    const float K1c = 0.08838834764831845f * 1.44269504088896340f;
    const float K2c = 1.44269504088896340f;

    for (int kt = 0; kt < 64; kt++) {
        const uint32_t stb = sb + (uint32_t)(SM_ST0 + (kt & 3) * STAGE_SZ);
        const uint32_t vtb = stb + 17408u;
        const int k0 = kt * 64;
        if (kt) { CP_WAIT2(); __syncthreads(); }

        // conn -> registers (consumed one S-chunk later; latency hidden by mma)
        float2 cf0[8], cf1[8];
        #pragma unroll
        for (int nt = 0; nt < 8; nt++) {
            cf0[nt] = *(const float2*)(connR0 + k0 + nt * 8);
            cf1[nt] = *(const float2*)(connR1 + k0 + nt * 8);
        }

        float sacc[8][4];
        #pragma unroll
        for (int nt = 0; nt < 8; nt++) { sacc[nt][0]=sacc[nt][1]=sacc[nt][2]=sacc[nt][3]=0.f; }

        // ---- S chunk A: keys 0-31 ----
        #pragma unroll
        for (int s = 0; s < 8; s++) {
            #pragma unroll
            for (int p = 0; p < 2; p++) {
                uint32_t b0, b1, b2, b3;
                ldsm_x4(b0, b1, b2, b3, stb + (uint32_t)((p * 16 + r_l) * 272 + (16 * s + c_l) * 2));
                mma_f16(sacc[2 * p],     qf[s][0], qf[s][1], qf[s][2], qf[s][3], b0, b1);
                mma_f16(sacc[2 * p + 1], qf[s][0], qf[s][1], qf[s][2], qf[s][3], b2, b3);
            }
        }
        // ---- S chunk B: keys 32-63 ----
        #pragma unroll
        for (int s = 0; s < 8; s++) {
            #pragma unroll
            for (int p = 2; p < 4; p++) {
                uint32_t b0, b1, b2, b3;
                ldsm_x4(b0, b1, b2, b3, stb + (uint32_t)((p * 16 + r_l) * 272 + (16 * s + c_l) * 2));
                mma_f16(sacc[2 * p],     qf[s][0], qf[s][1], qf[s][2], qf[s][3], b0, b1);
                mma_f16(sacc[2 * p + 1], qf[s][0], qf[s][1], qf[s][2], qf[s][3], b2, b3);
            }
        }

        // ---- epilogue A ----
        #pragma unroll
        for (int nt = 0; nt < 4; nt++) {
            sacc[nt][0] = ex2f(fmaf(sacc[nt][0], K1c, cf0[nt].x * K2c));
            sacc[nt][1] = ex2f(fmaf(sacc[nt][1], K1c, cf0[nt].y * K2c));
            sacc[nt][2] = ex2f(fmaf(sacc[nt][2], K1c, cf1[nt].x * K2c));
            sacc[nt][3] = ex2f(fmaf(sacc[nt][3], K1c, cf1[nt].y * K2c));
            l0 += sacc[nt][0] + sacc[nt][1];
            l1 += sacc[nt][2] + sacc[nt][3];
        }
        // ---- PV chunk A ----
        #pragma unroll
        for (int kk = 0; kk < 2; kk++) {
            const uint32_t a0 = pack_h2(sacc[2*kk][0],   sacc[2*kk][1]);
            const uint32_t a1 = pack_h2(sacc[2*kk][2],   sacc[2*kk][3]);
            const uint32_t a2 = pack_h2(sacc[2*kk+1][0], sacc[2*kk+1][1]);
            const uint32_t a3 = pack_h2(sacc[2*kk+1][2], sacc[2*kk+1][3]);
            #pragma unroll
            for (int p = 0; p < 8; p++) {
                uint32_t b0, b1, b2, b3;
                ldsm_x4(b0, b1, b2, b3, vtb + (uint32_t)((p * 16 + r_l) * 144 + (16 * kk + c_l) * 2));
                mma_f16(o[2 * p],     a0, a1, a2, a3, b0, b1);
                mma_f16(o[2 * p + 1], a0, a1, a2, a3, b2, b3);
            }
        }
        // ---- epilogue B ----
        #pragma unroll
        for (int nt = 4; nt < 8; nt++) {
            sacc[nt][0] = ex2f(fmaf(sacc[nt][0], K1c, cf0[nt].x * K2c));
            sacc[nt][1] = ex2f(fmaf(sacc[nt][1], K1c, cf0[nt].y * K2c));
            sacc[nt][2] = ex2f(fmaf(sacc[nt][2], K1c, cf1[nt].x * K2c));
            sacc[nt][3] = ex2f(fmaf(sacc[nt][3], K1c, cf1[nt].y * K2c));
            l0 += sacc[nt][0] + sacc[nt][1];
            l1 += sacc[nt][2] + sacc[nt][3];
        }
        // ---- PV chunk B ----
        #pragma unroll
        for (int kk = 2; kk < 4; kk++) {
            const uint32_t a0 = pack_h2(sacc[2*kk][0],   sacc[2*kk][1]);
            const uint32_t a1 = pack_h2(sacc[2*kk][2],   sacc[2*kk][3]);
            const uint32_t a2 = pack_h2(sacc[2*kk+1][0], sacc[2*kk+1][1]);
            const uint32_t a3 = pack_h2(sacc[2*kk+1][2], sacc[2*kk+1][3]);
            #pragma unroll
            for (int p = 0; p < 8; p++) {
                uint32_t b0, b1, b2, b3;
                ldsm_x4(b0, b1, b2, b3, vtb + (uint32_t)((p * 16 + r_l) * 144 + (16 * kk + c_l) * 2));
                mma_f16(o[2 * p],     a0, a1, a2, a3, b0, b1);
                mma_f16(o[2 * p + 1], a0, a1, a2, a3, b2, b3);
            }
        }

        // prefetch stage kt+3 (writes stage (kt-1)&3 — all warps are past the
        // top-of-tile barrier, so no one is still reading it)
        if (kt + 3 < 64) load_stage(sb, (kt + 3) & 3, b, (kt + 3) * 64, tid);
        CP_COMMIT();
    }

    l0 += __shfl_xor_sync(0xffffffffu, l0, 1);
    l0 += __shfl_xor_sync(0xffffffffu, l0, 2);
    l1 += __shfl_xor_sync(0xffffffffu, l1, 1);
    l1 += __shfl_xor_sync(0xffffffffu, l1, 2);
    const float r0 = 1.f / l0, r1 = 1.f / l1;
    float* H0 = g_H + ((size_t)(b * NA + q0 + qw + g)) * ND;
    float* H1 = H0 + 8 * ND;
    #pragma unroll
    for (int nt = 0; nt < 16; nt++) {
        *(float2*)(H0 + nt * 8 + 2 * t) = make_float2(o[nt][0] * r0, o[nt][1] * r0);
        *(float2*)(H1 + nt * 8 + 2 * t) = make_float2(o[nt][2] * r1, o[nt][3] * r1);
    }
}

// ======================= Kernel 3: MLP via mma (trans-B) =======================
#define MLP_SMEM (4 * 34816 + 4 * 512)

__global__ __launch_bounds__(256, 1)
void mlp_kernel(const float* __restrict__ W1, const float* __restrict__ b1,
                const float* __restrict__ W2, const float* __restrict__ b2,
                const float* __restrict__ gamma, const float* __restrict__ beta,
                float* __restrict__ out) {
    extern __shared__ __align__(16) char smem[];
    const uint32_t sb = smem_u32(smem);
    const int tid = threadIdx.x;
    const int w = tid >> 5, lane = tid & 31;
    const int g = lane >> 2, t = lane & 3;
    const int tr_r = lane & 15, tr_c = (lane & 16) >> 1;
    const int row0 = blockIdx.x * 128;
    const int qw = w * 16;

    float* sb1 = (float*)(smem + 139264);
    float* sb2 = sb1 + 128;
    float* sgm = sb2 + 128;
    float* sbt = sgm + 128;

    cvt_w(smem + 0,     W1, tid);
    cvt_w(smem + 34816, W2, tid);
    if (tid < 128) {
        sb1[tid] = b1[tid]; sb2[tid] = b2[tid];
        sgm[tid] = gamma[tid]; sbt[tid] = beta[tid];
    }
    #pragma unroll 4
    for (int it = 0; it < 16; it++) {
        const int i = tid + it * 256;
        const int r = i >> 5, c4 = (i & 31) * 4;
        const float4 v = *(const float4*)(g_H + (size_t)(row0 + r) * ND + c4);
        uint2 u;
        u.x = pack_h2(swishf(v.x), swishf(v.y));
        u.y = pack_h2(swishf(v.z), swishf(v.w));
        *(uint2*)(smem + 69632 + r * 272 + c4 * 2) = u;
    }
    __syncthreads();

    uint32_t hf[8][4];
    #pragma unroll
    for (int s = 0; s < 8; s++) {
        const char* base = smem + 69632 + (qw + g) * 272 + (16 * s + 2 * t) * 2;
        hf[s][0] = *(const uint32_t*)(base);
        hf[s][1] = *(const uint32_t*)(base + 8 * 272);
        hf[s][2] = *(const uint32_t*)(base + 16);
        hf[s][3] = *(const uint32_t*)(base + 8 * 272 + 16);
    }

    float o1[16][4];
    #pragma unroll
    for (int nt = 0; nt < 16; nt++) { o1[nt][0]=o1[nt][1]=o1[nt][2]=o1[nt][3]=0.f; }
    #pragma unroll
    for (int s = 0; s < 8; s++) {
        #pragma unroll
        for (int p = 0; p < 8; p++) {
            uint32_t b0v, b1v, b2v, b3v;
            ldsm_x4_t(b0v, b1v, b2v, b3v, sb + (uint32_t)((16 * s + tr_r) * 272 + (p * 16 + tr_c) * 2));
            mma_f16(o1[2 * p],     hf[s][0], hf[s][1], hf[s][2], hf[s][3], b0v, b1v);
            mma_f16(o1[2 * p + 1], hf[s][0], hf[s][1], hf[s][2], hf[s][3], b2v, b3v);
        }
    }
    #pragma unroll
    for (int nt = 0; nt < 16; nt++) {
        const float2 bb = *(const float2*)(sb1 + nt * 8 + 2 * t);
        const float v0 = swishf(o1[nt][0] + bb.x), v1 = swishf(o1[nt][1] + bb.y);
        const float v2 = swishf(o1[nt][2] + bb.x), v3 = swishf(o1[nt][3] + bb.y);
        *(uint32_t*)(smem + 104448 + (qw + g) * 272 + (nt * 8 + 2 * t) * 2)     = pack_h2(v0, v1);
        *(uint32_t*)(smem + 104448 + (qw + g + 8) * 272 + (nt * 8 + 2 * t) * 2) = pack_h2(v2, v3);
    }
    __syncwarp();

    uint32_t mf[8][4];
    #pragma unroll
    for (int s = 0; s < 8; s++) {
        const char* base = smem + 104448 + (qw + g) * 272 + (16 * s + 2 * t) * 2;
        mf[s][0] = *(const uint32_t*)(base);
        mf[s][1] = *(const uint32_t*)(base + 8 * 272);
        mf[s][2] = *(const uint32_t*)(base + 16);
        mf[s][3] = *(const uint32_t*)(base + 8 * 272 + 16);
    }

    float o2[16][4];
    #pragma unroll
    for (int nt = 0; nt < 16; nt++) { o2[nt][0]=o2[nt][1]=o2[nt][2]=o2[nt][3]=0.f; }
    #pragma unroll
    for (int s = 0; s < 8; s++) {
        #pragma unroll
        for (int p = 0; p < 8; p++) {
            uint32_t b0v, b1v, b2v, b3v;
            ldsm_x4_t(b0v, b1v, b2v, b3v, sb + 34816u + (uint32_t)((16 * s + tr_r) * 272 + (p * 16 + tr_c) * 2));
            mma_f16(o2[2 * p],     mf[s][0], mf[s][1], mf[s][2], mf[s][3], b0v, b1v);
            mma_f16(o2[2 * p + 1], mf[s][0], mf[s][1], mf[s][2], mf[s][3], b2v, b3v);
        }
    }
    float sum0 = 0.f, sq0 = 0.f, sum1 = 0.f, sq1 = 0.f;
    #pragma unroll
    for (int nt = 0; nt < 16; nt++) {
        const float2 bb = *(const float2*)(sb2 + nt * 8 + 2 * t);
        o2[nt][0] += bb.x; o2[nt][1] += bb.y;
        o2[nt][2] += bb.x; o2[nt][3] += bb.y;
        sum0 += o2[nt][0] + o2[nt][1];
        sq0  += o2[nt][0] * o2[nt][0] + o2[nt][1] * o2[nt][1];
        sum1 += o2[nt][2] + o2[nt][3];
        sq1  += o2[nt][2] * o2[nt][2] + o2[nt][3] * o2[nt][3];
    }
    #pragma unroll
    for (int off = 1; off <= 2; off <<= 1) {
        sum0 += __shfl_xor_sync(0xffffffffu, sum0, off);
        sq0  += __shfl_xor_sync(0xffffffffu, sq0,  off);
        sum1 += __shfl_xor_sync(0xffffffffu, sum1, off);
        sq1  += __shfl_xor_sync(0xffffffffu, sq1,  off);
    }
    const float mu0 = sum0 * 0.0078125f, mu1 = sum1 * 0.0078125f;
    const float rs0 = rsqrtf(sq0 * 0.0078125f - mu0 * mu0 + 1e-5f);
    const float rs1 = rsqrtf(sq1 * 0.0078125f - mu1 * mu1 + 1e-5f);
    float* O0 = out + (size_t)(row0 + qw + g) * ND;
    float* O1 = O0 + 8 * ND;
    #pragma unroll
    for (int nt = 0; nt < 16; nt++) {
        const float2 gm = *(const float2*)(sgm + nt * 8 + 2 * t);
        const float2 bt = *(const float2*)(sbt + nt * 8 + 2 * t);
        *(float2*)(O0 + nt * 8 + 2 * t) = make_float2(
            fmaf((o2[nt][0] - mu0) * rs0, gm.x, bt.x),
            fmaf((o2[nt][1] - mu0) * rs0, gm.y, bt.y));
        *(float2*)(O1 + nt * 8 + 2 * t) = make_float2(
            fmaf((o2[nt][2] - mu1) * rs1, gm.x, bt.x),
            fmaf((o2[nt][3] - mu1) * rs1, gm.y, bt.y));
    }
}

extern "C" void kernel_launch(void* const* d_in, const int* in_sizes, int n_in,
                              void* d_out, int out_size) {
    const float* x     = (const float*)d_in[0];
    const float* conn  = (const float*)d_in[1];
    const float* Wq    = (const float*)d_in[2];
    const float* Wk    = (const float*)d_in[3];
    const float* Wv    = (const float*)d_in[4];
    const float* W1    = (const float*)d_in[5];
    const float* b1    = (const float*)d_in[6];
    const float* W2    = (const float*)d_in[7];
    const float* b2    = (const float*)d_in[8];
    const float* gamma = (const float*)d_in[9];
    const float* beta  = (const float*)d_in[10];
    float* out = (float*)d_out;

    static bool attr_done = false;
    if (!attr_done) {
        cudaFuncSetAttribute(proj_kernel, cudaFuncAttributeMaxDynamicSharedMemorySize, PROJ_SMEM);
        cudaFuncSetAttribute(attn_kernel, cudaFuncAttributeMaxDynamicSharedMemorySize, ATTN_SMEM);
        cudaFuncSetAttribute(mlp_kernel,  cudaFuncAttributeMaxDynamicSharedMemorySize, MLP_SMEM);
        attr_done = true;
    }

    proj_kernel<<<128, 256, PROJ_SMEM>>>(x, Wq, Wk, Wv);
    attn_kernel<<<dim3(32, 4), 256, ATTN_SMEM>>>(conn);
    mlp_kernel<<<128, 256, MLP_SMEM>>>(W1, b1, W2, b2, gamma, beta, out);
}

// round 10
// speedup vs baseline: 1.5129x; 1.5129x over previous
#include <cuda_runtime.h>
#include <cuda_fp16.h>
#include <cstdint>

#define NB 4
#define NA 4096
#define ND 128

__device__ __half g_Qh[NB * NA * ND];
__device__ __half g_Kh[NB * NA * ND];
__device__ __half g_Vt[NB * ND * NA];   // [b][d][a]
__device__ float  g_H [NB * NA * ND];

// ======================= helpers =======================
__device__ __forceinline__ uint32_t smem_u32(const void* p) {
    uint32_t a;
    asm("{ .reg .u64 t; cvta.to.shared.u64 t, %1; cvt.u32.u64 %0, t; }" : "=r"(a) : "l"(p));
    return a;
}
__device__ __forceinline__ void mma_f16(float c[4],
                                        uint32_t a0, uint32_t a1, uint32_t a2, uint32_t a3,
                                        uint32_t b0, uint32_t b1) {
    asm volatile(
        "mma.sync.aligned.m16n8k16.row.col.f32.f16.f16.f32 "
        "{%0,%1,%2,%3},{%4,%5,%6,%7},{%8,%9},{%0,%1,%2,%3};\n"
        : "+f"(c[0]), "+f"(c[1]), "+f"(c[2]), "+f"(c[3])
        : "r"(a0), "r"(a1), "r"(a2), "r"(a3), "r"(b0), "r"(b1));
}
__device__ __forceinline__ void ldsm_x4(uint32_t& r0, uint32_t& r1, uint32_t& r2, uint32_t& r3,
                                        uint32_t addr) {
    asm volatile("ldmatrix.sync.aligned.m8n8.x4.shared.b16 {%0,%1,%2,%3}, [%4];"
                 : "=r"(r0), "=r"(r1), "=r"(r2), "=r"(r3) : "r"(addr));
}
__device__ __forceinline__ void ldsm_x4_t(uint32_t& r0, uint32_t& r1, uint32_t& r2, uint32_t& r3,
                                          uint32_t addr) {
    asm volatile("ldmatrix.sync.aligned.m8n8.x4.trans.shared.b16 {%0,%1,%2,%3}, [%4];"
                 : "=r"(r0), "=r"(r1), "=r"(r2), "=r"(r3) : "r"(addr));
}
__device__ __forceinline__ void cpa16(uint32_t dst, const void* src) {
    asm volatile("cp.async.cg.shared.global [%0], [%1], 16;" :: "r"(dst), "l"(src) : "memory");
}
#define CP_COMMIT() asm volatile("cp.async.commit_group;" ::: "memory")
#define CP_WAIT1()  asm volatile("cp.async.wait_group 1;" ::: "memory")

__device__ __forceinline__ float ex2f(float x) {
    float y; asm("ex2.approx.ftz.f32 %0, %1;" : "=f"(y) : "f"(x)); return y;
}
__device__ __forceinline__ uint32_t pack_h2(float lo, float hi) {
    __half2 h = __floats2half2_rn(lo, hi);
    return *reinterpret_cast<uint32_t*>(&h);
}
__device__ __forceinline__ float swishf(float v) { return v / (1.f + __expf(-v)); }

// convert a 128x128 fp32 weight W (row-major [k][n]) into smem fp16 [k][n], 272B row stride
__device__ __forceinline__ void cvt_w(char* dst, const float* __restrict__ W, int tid) {
    #pragma unroll
    for (int it = 0; it < 16; it++) {
        const int i = tid + it * 256;
        const int r = i >> 5, c4 = (i & 31) * 4;
        const float4 v = *(const float4*)(W + (size_t)i * 4);
        uint2 u;
        u.x = pack_h2(v.x, v.y);
        u.y = pack_h2(v.z, v.w);
        *(uint2*)(dst + r * 272 + c4 * 2) = u;
    }
}

// ======================= Kernel 1: projections via mma (trans-B) =======================
#define PROJ_SMEM (5 * 34816)

__global__ __launch_bounds__(256, 1)
void proj_kernel(const float* __restrict__ x,
                 const float* __restrict__ Wq,
                 const float* __restrict__ Wk,
                 const float* __restrict__ Wv) {
    extern __shared__ __align__(16) char smem[];
    const uint32_t sb = smem_u32(smem);
    const int tid = threadIdx.x;
    const int w = tid >> 5, lane = tid & 31;
    const int g = lane >> 2, t = lane & 3;
    const int tr_r = lane & 15, tr_c = (lane & 16) >> 1;
    const int row0 = blockIdx.x * 128;
    const int b = row0 >> 12, a0 = row0 & (NA - 1);
    const int qw = w * 16;

    __half* sVst = (__half*)(smem + 139264);

    #pragma unroll 4
    for (int it = 0; it < 16; it++) {
        const int i = tid + it * 256;
        const int r = i >> 5, c4 = (i & 31) * 4;
        const float4 v = *(const float4*)(x + (size_t)(row0 + r) * ND + c4);
        uint2 u;
        u.x = pack_h2(v.x, v.y);
        u.y = pack_h2(v.z, v.w);
        *(uint2*)(smem + r * 272 + c4 * 2) = u;
    }
    cvt_w(smem + 34816,  Wq, tid);
    cvt_w(smem + 69632,  Wk, tid);
    cvt_w(smem + 104448, Wv, tid);
    __syncthreads();

    uint32_t xf[8][4];
    #pragma unroll
    for (int s = 0; s < 8; s++) {
        const char* base = (const char*)smem + (qw + g) * 272 + (16 * s + 2 * t) * 2;
        xf[s][0] = *(const uint32_t*)(base);
        xf[s][1] = *(const uint32_t*)(base + 8 * 272);
        xf[s][2] = *(const uint32_t*)(base + 16);
        xf[s][3] = *(const uint32_t*)(base + 8 * 272 + 16);
    }

    const int gr0 = row0 + qw + g;
    #pragma unroll
    for (int m = 0; m < 3; m++) {
        const uint32_t wb = sb + 34816u * (1 + m);
        float o[16][4];
        #pragma unroll
        for (int nt = 0; nt < 16; nt++) { o[nt][0]=o[nt][1]=o[nt][2]=o[nt][3]=0.f; }
        #pragma unroll
        for (int s = 0; s < 8; s++) {
            #pragma unroll
            for (int p = 0; p < 8; p++) {
                uint32_t b0, b1, b2, b3;
                ldsm_x4_t(b0, b1, b2, b3, wb + (uint32_t)((16 * s + tr_r) * 272 + (p * 16 + tr_c) * 2));
                mma_f16(o[2 * p],     xf[s][0], xf[s][1], xf[s][2], xf[s][3], b0, b1);
                mma_f16(o[2 * p + 1], xf[s][0], xf[s][1], xf[s][2], xf[s][3], b2, b3);
            }
        }
        if (m < 2) {
            __half* dst = (m == 0) ? g_Qh : g_Kh;
            #pragma unroll
            for (int nt = 0; nt < 16; nt++) {
                *(uint32_t*)(dst + (size_t)gr0 * ND + nt * 8 + 2 * t)       = pack_h2(o[nt][0], o[nt][1]);
                *(uint32_t*)(dst + (size_t)(gr0 + 8) * ND + nt * 8 + 2 * t) = pack_h2(o[nt][2], o[nt][3]);
            }
        } else {
            #pragma unroll
            for (int nt = 0; nt < 16; nt++) {
                *(uint32_t*)((char*)sVst + (qw + g) * 272 + (nt * 8 + 2 * t) * 2)     = pack_h2(o[nt][0], o[nt][1]);
                *(uint32_t*)((char*)sVst + (qw + g + 8) * 272 + (nt * 8 + 2 * t) * 2) = pack_h2(o[nt][2], o[nt][3]);
            }
        }
    }
    __syncthreads();
    const int c = tid & 127, dgrp = tid >> 7;
    #pragma unroll 4
    for (int k = 0; k < 64; k++) {
        const int dd = dgrp * 64 + k;
        g_Vt[((size_t)(b * ND + dd)) * NA + a0 + c] = sVst[c * 136 + dd];
    }
}

// ======================= Kernel 2: flash attention (3-stage ring, conn via cp.async) =======================
// stage = K (17408) + V (18432) + conn (34816) = 70656 bytes
#define STAGE_SZ 70656
#define CONN_OFF 35840
#define ATTN_SMEM (3 * STAGE_SZ)     // 211968
// Q staged temporarily inside slot 2 (dead after qf extraction)
#define SM_QTMP  (2 * STAGE_SZ)

__device__ __forceinline__ void load_stage(uint32_t sb, int slot, int b, int q0, int k0, int tid,
                                           const float* __restrict__ conn) {
    const uint32_t base = sb + (uint32_t)(slot * STAGE_SZ);
    const __half* Kg = g_Kh + ((size_t)(b * NA + k0)) * ND;
    #pragma unroll
    for (int i = tid; i < 1024; i += 256) {
        const int r = i >> 4, c = i & 15;
        cpa16(base + (uint32_t)(r * 272 + c * 16), Kg + r * ND + c * 8);
    }
    const __half* Vg = g_Vt + ((size_t)(b * ND)) * NA + k0;
    #pragma unroll
    for (int i = tid; i < 1024; i += 256) {
        const int r = i >> 3, c = i & 7;
        cpa16(base + (uint32_t)(17408 + r * 144 + c * 16), Vg + (size_t)r * NA + c * 8);
    }
    const float* Cg = conn + ((size_t)(b * NA + q0)) * NA + k0;
    #pragma unroll
    for (int i = tid; i < 2048; i += 256) {
        const int r = i >> 4, c = i & 15;
        cpa16(base + (uint32_t)(CONN_OFF + r * 272 + c * 16), Cg + (size_t)r * NA + c * 4);
    }
}

__global__ __launch_bounds__(256, 1)
void attn_kernel(const float* __restrict__ conn) {
    extern __shared__ __align__(16) char smem[];
    const uint32_t sb = smem_u32(smem);
    const int tid = threadIdx.x;
    const int w = tid >> 5, lane = tid & 31;
    const int g = lane >> 2, t = lane & 3;
    const int b = blockIdx.y;
    const int q0 = blockIdx.x * 128;
    const int qw = w * 16;
    const int r_l = ((lane & 16) >> 1) + (lane & 7);
    const int c_l = (lane & 8);

    // prologue: Q (into slot2 footprint) + stage0 -> g0; stage1 -> g1
    {
        const __half* Qg = g_Qh + ((size_t)(b * NA + q0)) * ND;
        #pragma unroll
        for (int i = tid; i < 2048; i += 256) {
            const int r = i >> 4, c = i & 15;
            cpa16(sb + (uint32_t)(SM_QTMP + r * 272 + c * 16), Qg + r * ND + c * 8);
        }
    }
    load_stage(sb, 0, b, q0, 0, tid, conn);
    CP_COMMIT();
    load_stage(sb, 1, b, q0, 64, tid, conn);
    CP_COMMIT();

    CP_WAIT1();          // g0 done: Q + stage0 ready
    __syncthreads();

    uint32_t qf[8][4];
    #pragma unroll
    for (int s = 0; s < 8; s++) {
        const char* base = smem + SM_QTMP + (qw + g) * 272 + (16 * s + 2 * t) * 2;
        qf[s][0] = *(const uint32_t*)(base);
        qf[s][1] = *(const uint32_t*)(base + 8 * 272);
        qf[s][2] = *(const uint32_t*)(base + 16);
        qf[s][3] = *(const uint32_t*)(base + 8 * 272 + 16);
    }
    __syncthreads();     // all warps done with Q before slot2 is overwritten

    float o[16][4];
    #pragma unroll
    for (int nt = 0; nt < 16; nt++) { o[nt][0]=o[nt][1]=o[nt][2]=o[nt][3]=0.f; }
    float l0 = 0.f, l1 = 0.f;

    const float K1c = 0.08838834764831845f * 1.44269504088896340f;
    const float K2c = 1.44269504088896340f;

    int slot = 0;
    for (int kt = 0; kt < 64; kt++) {
        const uint32_t stb = sb + (uint32_t)(slot * STAGE_SZ);
        const uint32_t vtb = stb + 17408u;
        if (kt) { CP_WAIT1(); __syncthreads(); }

        // prefetch tile kt+2 into slot (kt+2)%3 == (kt-1)%3 (safe: barrier above
        // proves all warps finished reading tile kt-1)
        {
            int ps = slot + 2; if (ps >= 3) ps -= 3;
            if (kt + 2 < 64) load_stage(sb, ps, b, q0, (kt + 2) * 64, tid, conn);
            CP_COMMIT();
        }

        float sacc[8][4];
        #pragma unroll
        for (int nt = 0; nt < 8; nt++) { sacc[nt][0]=sacc[nt][1]=sacc[nt][2]=sacc[nt][3]=0.f; }

        // ---- S chunk A: keys 0-31 ----
        #pragma unroll
        for (int s = 0; s < 8; s++) {
            #pragma unroll
            for (int p = 0; p < 2; p++) {
                uint32_t b0, b1, b2, b3;
                ldsm_x4(b0, b1, b2, b3, stb + (uint32_t)((p * 16 + r_l) * 272 + (16 * s + c_l) * 2));
                mma_f16(sacc[2 * p],     qf[s][0], qf[s][1], qf[s][2], qf[s][3], b0, b1);
                mma_f16(sacc[2 * p + 1], qf[s][0], qf[s][1], qf[s][2], qf[s][3], b2, b3);
            }
        }
        // ---- S chunk B: keys 32-63 ----
        #pragma unroll
        for (int s = 0; s < 8; s++) {
            #pragma unroll
            for (int p = 2; p < 4; p++) {
                uint32_t b0, b1, b2, b3;
                ldsm_x4(b0, b1, b2, b3, stb + (uint32_t)((p * 16 + r_l) * 272 + (16 * s + c_l) * 2));
                mma_f16(sacc[2 * p],     qf[s][0], qf[s][1], qf[s][2], qf[s][3], b0, b1);
                mma_f16(sacc[2 * p + 1], qf[s][0], qf[s][1], qf[s][2], qf[s][3], b2, b3);
            }
        }

        const float* c0p = (const float*)(smem + slot * STAGE_SZ + CONN_OFF) + (qw + g) * 68 + 2 * t;
        const float* c1p = c0p + 8 * 68;

        // ---- epilogue A ----
        #pragma unroll
        for (int nt = 0; nt < 4; nt++) {
            const float2 v0 = *(const float2*)(c0p + nt * 8);
            const float2 v1 = *(const float2*)(c1p + nt * 8);
            sacc[nt][0] = ex2f(fmaf(sacc[nt][0], K1c, v0.x * K2c));
            sacc[nt][1] = ex2f(fmaf(sacc[nt][1], K1c, v0.y * K2c));
            sacc[nt][2] = ex2f(fmaf(sacc[nt][2], K1c, v1.x * K2c));
            sacc[nt][3] = ex2f(fmaf(sacc[nt][3], K1c, v1.y * K2c));
            l0 += sacc[nt][0] + sacc[nt][1];
            l1 += sacc[nt][2] + sacc[nt][3];
        }
        // ---- PV chunk A ----
        #pragma unroll
        for (int kk = 0; kk < 2; kk++) {
            const uint32_t a0 = pack_h2(sacc[2*kk][0],   sacc[2*kk][1]);
            const uint32_t a1 = pack_h2(sacc[2*kk][2],   sacc[2*kk][3]);
            const uint32_t a2 = pack_h2(sacc[2*kk+1][0], sacc[2*kk+1][1]);
            const uint32_t a3 = pack_h2(sacc[2*kk+1][2], sacc[2*kk+1][3]);
            #pragma unroll
            for (int p = 0; p < 8; p++) {
                uint32_t b0, b1, b2, b3;
                ldsm_x4(b0, b1, b2, b3, vtb + (uint32_t)((p * 16 + r_l) * 144 + (16 * kk + c_l) * 2));
                mma_f16(o[2 * p],     a0, a1, a2, a3, b0, b1);
                mma_f16(o[2 * p + 1], a0, a1, a2, a3, b2, b3);
            }
        }
        // ---- epilogue B ----
        #pragma unroll
        for (int nt = 4; nt < 8; nt++) {
            const float2 v0 = *(const float2*)(c0p + nt * 8);
            const float2 v1 = *(const float2*)(c1p + nt * 8);
            sacc[nt][0] = ex2f(fmaf(sacc[nt][0], K1c, v0.x * K2c));
            sacc[nt][1] = ex2f(fmaf(sacc[nt][1], K1c, v0.y * K2c));
            sacc[nt][2] = ex2f(fmaf(sacc[nt][2], K1c, v1.x * K2c));
            sacc[nt][3] = ex2f(fmaf(sacc[nt][3], K1c, v1.y * K2c));
            l0 += sacc[nt][0] + sacc[nt][1];
            l1 += sacc[nt][2] + sacc[nt][3];
        }
        // ---- PV chunk B ----
        #pragma unroll
        for (int kk = 2; kk < 4; kk++) {
            const uint32_t a0 = pack_h2(sacc[2*kk][0],   sacc[2*kk][1]);
            const uint32_t a1 = pack_h2(sacc[2*kk][2],   sacc[2*kk][3]);
            const uint32_t a2 = pack_h2(sacc[2*kk+1][0], sacc[2*kk+1][1]);
            const uint32_t a3 = pack_h2(sacc[2*kk+1][2], sacc[2*kk+1][3]);
            #pragma unroll
            for (int p = 0; p < 8; p++) {
                uint32_t b0, b1, b2, b3;
                ldsm_x4(b0, b1, b2, b3, vtb + (uint32_t)((p * 16 + r_l) * 144 + (16 * kk + c_l) * 2));
                mma_f16(o[2 * p],     a0, a1, a2, a3, b0, b1);
                mma_f16(o[2 * p + 1], a0, a1, a2, a3, b2, b3);
            }
        }

        slot++; if (slot >= 3) slot = 0;
    }

    l0 += __shfl_xor_sync(0xffffffffu, l0, 1);
    l0 += __shfl_xor_sync(0xffffffffu, l0, 2);
    l1 += __shfl_xor_sync(0xffffffffu, l1, 1);
    l1 += __shfl_xor_sync(0xffffffffu, l1, 2);
    const float r0 = 1.f / l0, r1 = 1.f / l1;
    float* H0 = g_H + ((size_t)(b * NA + q0 + qw + g)) * ND;
    float* H1 = H0 + 8 * ND;
    #pragma unroll
    for (int nt = 0; nt < 16; nt++) {
        *(float2*)(H0 + nt * 8 + 2 * t) = make_float2(o[nt][0] * r0, o[nt][1] * r0);
        *(float2*)(H1 + nt * 8 + 2 * t) = make_float2(o[nt][2] * r1, o[nt][3] * r1);
    }
}

// ======================= Kernel 3: MLP via mma (trans-B) =======================
#define MLP_SMEM (4 * 34816 + 4 * 512)

__global__ __launch_bounds__(256, 1)
void mlp_kernel(const float* __restrict__ W1, const float* __restrict__ b1,
                const float* __restrict__ W2, const float* __restrict__ b2,
                const float* __restrict__ gamma, const float* __restrict__ beta,
                float* __restrict__ out) {
    extern __shared__ __align__(16) char smem[];
    const uint32_t sb = smem_u32(smem);
    const int tid = threadIdx.x;
    const int w = tid >> 5, lane = tid & 31;
    const int g = lane >> 2, t = lane & 3;
    const int tr_r = lane & 15, tr_c = (lane & 16) >> 1;
    const int row0 = blockIdx.x * 128;
    const int qw = w * 16;

    float* sb1 = (float*)(smem + 139264);
    float* sb2 = sb1 + 128;
    float* sgm = sb2 + 128;
    float* sbt = sgm + 128;

    cvt_w(smem + 0,     W1, tid);
    cvt_w(smem + 34816, W2, tid);
    if (tid < 128) {
        sb1[tid] = b1[tid]; sb2[tid] = b2[tid];
        sgm[tid] = gamma[tid]; sbt[tid] = beta[tid];
    }
    #pragma unroll 4
    for (int it = 0; it < 16; it++) {
        const int i = tid + it * 256;
        const int r = i >> 5, c4 = (i & 31) * 4;
        const float4 v = *(const float4*)(g_H + (size_t)(row0 + r) * ND + c4);
        uint2 u;
        u.x = pack_h2(swishf(v.x), swishf(v.y));
        u.y = pack_h2(swishf(v.z), swishf(v.w));
        *(uint2*)(smem + 69632 + r * 272 + c4 * 2) = u;
    }
    __syncthreads();

    uint32_t hf[8][4];
    #pragma unroll
    for (int s = 0; s < 8; s++) {
        const char* base = smem + 69632 + (qw + g) * 272 + (16 * s + 2 * t) * 2;
        hf[s][0] = *(const uint32_t*)(base);
        hf[s][1] = *(const uint32_t*)(base + 8 * 272);
        hf[s][2] = *(const uint32_t*)(base + 16);
        hf[s][3] = *(const uint32_t*)(base + 8 * 272 + 16);
    }

    float o1[16][4];
    #pragma unroll
    for (int nt = 0; nt < 16; nt++) { o1[nt][0]=o1[nt][1]=o1[nt][2]=o1[nt][3]=0.f; }
    #pragma unroll
    for (int s = 0; s < 8; s++) {
        #pragma unroll
        for (int p = 0; p < 8; p++) {
            uint32_t b0v, b1v, b2v, b3v;
            ldsm_x4_t(b0v, b1v, b2v, b3v, sb + (uint32_t)((16 * s + tr_r) * 272 + (p * 16 + tr_c) * 2));
            mma_f16(o1[2 * p],     hf[s][0], hf[s][1], hf[s][2], hf[s][3], b0v, b1v);
            mma_f16(o1[2 * p + 1], hf[s][0], hf[s][1], hf[s][2], hf[s][3], b2v, b3v);
        }
    }
    #pragma unroll
    for (int nt = 0; nt < 16; nt++) {
        const float2 bb = *(const float2*)(sb1 + nt * 8 + 2 * t);
        const float v0 = swishf(o1[nt][0] + bb.x), v1 = swishf(o1[nt][1] + bb.y);
        const float v2 = swishf(o1[nt][2] + bb.x), v3 = swishf(o1[nt][3] + bb.y);
        *(uint32_t*)(smem + 104448 + (qw + g) * 272 + (nt * 8 + 2 * t) * 2)     = pack_h2(v0, v1);
        *(uint32_t*)(smem + 104448 + (qw + g + 8) * 272 + (nt * 8 + 2 * t) * 2) = pack_h2(v2, v3);
    }
    __syncwarp();

    uint32_t mf[8][4];
    #pragma unroll
    for (int s = 0; s < 8; s++) {
        const char* base = smem + 104448 + (qw + g) * 272 + (16 * s + 2 * t) * 2;
        mf[s][0] = *(const uint32_t*)(base);
        mf[s][1] = *(const uint32_t*)(base + 8 * 272);
        mf[s][2] = *(const uint32_t*)(base + 16);
        mf[s][3] = *(const uint32_t*)(base + 8 * 272 + 16);
    }

    float o2[16][4];
    #pragma unroll
    for (int nt = 0; nt < 16; nt++) { o2[nt][0]=o2[nt][1]=o2[nt][2]=o2[nt][3]=0.f; }
    #pragma unroll
    for (int s = 0; s < 8; s++) {
        #pragma unroll
        for (int p = 0; p < 8; p++) {
            uint32_t b0v, b1v, b2v, b3v;
            ldsm_x4_t(b0v, b1v, b2v, b3v, sb + 34816u + (uint32_t)((16 * s + tr_r) * 272 + (p * 16 + tr_c) * 2));
            mma_f16(o2[2 * p],     mf[s][0], mf[s][1], mf[s][2], mf[s][3], b0v, b1v);
            mma_f16(o2[2 * p + 1], mf[s][0], mf[s][1], mf[s][2], mf[s][3], b2v, b3v);
        }
    }
    float sum0 = 0.f, sq0 = 0.f, sum1 = 0.f, sq1 = 0.f;
    #pragma unroll
    for (int nt = 0; nt < 16; nt++) {
        const float2 bb = *(const float2*)(sb2 + nt * 8 + 2 * t);
        o2[nt][0] += bb.x; o2[nt][1] += bb.y;
        o2[nt][2] += bb.x; o2[nt][3] += bb.y;
        sum0 += o2[nt][0] + o2[nt][1];
        sq0  += o2[nt][0] * o2[nt][0] + o2[nt][1] * o2[nt][1];
        sum1 += o2[nt][2] + o2[nt][3];
        sq1  += o2[nt][2] * o2[nt][2] + o2[nt][3] * o2[nt][3];
    }
    #pragma unroll
    for (int off = 1; off <= 2; off <<= 1) {
        sum0 += __shfl_xor_sync(0xffffffffu, sum0, off);
        sq0  += __shfl_xor_sync(0xffffffffu, sq0,  off);
        sum1 += __shfl_xor_sync(0xffffffffu, sum1, off);
        sq1  += __shfl_xor_sync(0xffffffffu, sq1,  off);
    }
    const float mu0 = sum0 * 0.0078125f, mu1 = sum1 * 0.0078125f;
    const float rs0 = rsqrtf(sq0 * 0.0078125f - mu0 * mu0 + 1e-5f);
    const float rs1 = rsqrtf(sq1 * 0.0078125f - mu1 * mu1 + 1e-5f);
    float* O0 = out + (size_t)(row0 + qw + g) * ND;
    float* O1 = O0 + 8 * ND;
    #pragma unroll
    for (int nt = 0; nt < 16; nt++) {
        const float2 gm = *(const float2*)(sgm + nt * 8 + 2 * t);
        const float2 bt = *(const float2*)(sbt + nt * 8 + 2 * t);
        *(float2*)(O0 + nt * 8 + 2 * t) = make_float2(
            fmaf((o2[nt][0] - mu0) * rs0, gm.x, bt.x),
            fmaf((o2[nt][1] - mu0) * rs0, gm.y, bt.y));
        *(float2*)(O1 + nt * 8 + 2 * t) = make_float2(
            fmaf((o2[nt][2] - mu1) * rs1, gm.x, bt.x),
            fmaf((o2[nt][3] - mu1) * rs1, gm.y, bt.y));
    }
}

extern "C" void kernel_launch(void* const* d_in, const int* in_sizes, int n_in,
                              void* d_out, int out_size) {
    const float* x     = (const float*)d_in[0];
    const float* conn  = (const float*)d_in[1];
    const float* Wq    = (const float*)d_in[2];
    const float* Wk    = (const float*)d_in[3];
    const float* Wv    = (const float*)d_in[4];
    const float* W1    = (const float*)d_in[5];
    const float* b1    = (const float*)d_in[6];
    const float* W2    = (const float*)d_in[7];
    const float* b2    = (const float*)d_in[8];
    const float* gamma = (const float*)d_in[9];
    const float* beta  = (const float*)d_in[10];
    float* out = (float*)d_out;

    static bool attr_done = false;
    if (!attr_done) {
        cudaFuncSetAttribute(proj_kernel, cudaFuncAttributeMaxDynamicSharedMemorySize, PROJ_SMEM);
        cudaFuncSetAttribute(attn_kernel, cudaFuncAttributeMaxDynamicSharedMemorySize, ATTN_SMEM);
        cudaFuncSetAttribute(mlp_kernel,  cudaFuncAttributeMaxDynamicSharedMemorySize, MLP_SMEM);
        attr_done = true;
    }

    proj_kernel<<<128, 256, PROJ_SMEM>>>(x, Wq, Wk, Wv);
    attn_kernel<<<dim3(32, 4), 256, ATTN_SMEM>>>(conn);
    mlp_kernel<<<128, 256, MLP_SMEM>>>(W1, b1, W2, b2, gamma, beta, out);
}

// round 11
// speedup vs baseline: 1.5503x; 1.0247x over previous
#include <cuda_runtime.h>
#include <cuda_fp16.h>
#include <cstdint>

#define NB 4
#define NA 4096
#define ND 128

__device__ __half g_Kh[NB * NA * ND];
__device__ __half g_Vt[NB * ND * NA];   // [b][d][a]

// ======================= helpers =======================
__device__ __forceinline__ uint32_t smem_u32(const void* p) {
    uint32_t a;
    asm("{ .reg .u64 t; cvta.to.shared.u64 t, %1; cvt.u32.u64 %0, t; }" : "=r"(a) : "l"(p));
    return a;
}
__device__ __forceinline__ void mma_f16(float c[4],
                                        uint32_t a0, uint32_t a1, uint32_t a2, uint32_t a3,
                                        uint32_t b0, uint32_t b1) {
    asm volatile(
        "mma.sync.aligned.m16n8k16.row.col.f32.f16.f16.f32 "
        "{%0,%1,%2,%3},{%4,%5,%6,%7},{%8,%9},{%0,%1,%2,%3};\n"
        : "+f"(c[0]), "+f"(c[1]), "+f"(c[2]), "+f"(c[3])
        : "r"(a0), "r"(a1), "r"(a2), "r"(a3), "r"(b0), "r"(b1));
}
__device__ __forceinline__ void ldsm_x4(uint32_t& r0, uint32_t& r1, uint32_t& r2, uint32_t& r3,
                                        uint32_t addr) {
    asm volatile("ldmatrix.sync.aligned.m8n8.x4.shared.b16 {%0,%1,%2,%3}, [%4];"
                 : "=r"(r0), "=r"(r1), "=r"(r2), "=r"(r3) : "r"(addr));
}
__device__ __forceinline__ void ldsm_x4_t(uint32_t& r0, uint32_t& r1, uint32_t& r2, uint32_t& r3,
                                          uint32_t addr) {
    asm volatile("ldmatrix.sync.aligned.m8n8.x4.trans.shared.b16 {%0,%1,%2,%3}, [%4];"
                 : "=r"(r0), "=r"(r1), "=r"(r2), "=r"(r3) : "r"(addr));
}
__device__ __forceinline__ void cpa16(uint32_t dst, const void* src) {
    asm volatile("cp.async.cg.shared.global [%0], [%1], 16;" :: "r"(dst), "l"(src) : "memory");
}
#define CP_COMMIT() asm volatile("cp.async.commit_group;" ::: "memory")
#define CP_WAIT1()  asm volatile("cp.async.wait_group 1;" ::: "memory")

__device__ __forceinline__ float ex2f(float x) {
    float y; asm("ex2.approx.ftz.f32 %0, %1;" : "=f"(y) : "f"(x)); return y;
}
__device__ __forceinline__ uint32_t pack_h2(float lo, float hi) {
    __half2 h = __floats2half2_rn(lo, hi);
    return *reinterpret_cast<uint32_t*>(&h);
}
__device__ __forceinline__ float swishf(float v) { return v / (1.f + __expf(-v)); }

// convert a 128x128 fp32 weight W (row-major [k][n]) into smem fp16 [k][n], 272B row stride
__device__ __forceinline__ void cvt_w(char* dst, const float* __restrict__ W, int tid) {
    #pragma unroll
    for (int it = 0; it < 16; it++) {
        const int i = tid + it * 256;
        const int r = i >> 5, c4 = (i & 31) * 4;
        const float4 v = *(const float4*)(W + (size_t)i * 4);
        uint2 u;
        u.x = pack_h2(v.x, v.y);
        u.y = pack_h2(v.z, v.w);
        *(uint2*)(dst + r * 272 + c4 * 2) = u;
    }
}

// ======================= Kernel 1: K/V projections via mma (trans-B) =======================
// smem: sX @0, sWk @34816, sWv @69632, sVst @104448
#define PROJ_SMEM (4 * 34816)

__global__ __launch_bounds__(256, 1)
void proj_kernel(const float* __restrict__ x,
                 const float* __restrict__ Wk,
                 const float* __restrict__ Wv) {
    extern __shared__ __align__(16) char smem[];
    const uint32_t sb = smem_u32(smem);
    const int tid = threadIdx.x;
    const int w = tid >> 5, lane = tid & 31;
    const int g = lane >> 2, t = lane & 3;
    const int tr_r = lane & 15, tr_c = (lane & 16) >> 1;
    const int row0 = blockIdx.x * 128;
    const int b = row0 >> 12, a0 = row0 & (NA - 1);
    const int qw = w * 16;

    __half* sVst = (__half*)(smem + 104448);

    #pragma unroll 4
    for (int it = 0; it < 16; it++) {
        const int i = tid + it * 256;
        const int r = i >> 5, c4 = (i & 31) * 4;
        const float4 v = *(const float4*)(x + (size_t)(row0 + r) * ND + c4);
        uint2 u;
        u.x = pack_h2(v.x, v.y);
        u.y = pack_h2(v.z, v.w);
        *(uint2*)(smem + r * 272 + c4 * 2) = u;
    }
    cvt_w(smem + 34816, Wk, tid);
    cvt_w(smem + 69632, Wv, tid);
    __syncthreads();

    uint32_t xf[8][4];
    #pragma unroll
    for (int s = 0; s < 8; s++) {
        const char* base = (const char*)smem + (qw + g) * 272 + (16 * s + 2 * t) * 2;
        xf[s][0] = *(const uint32_t*)(base);
        xf[s][1] = *(const uint32_t*)(base + 8 * 272);
        xf[s][2] = *(const uint32_t*)(base + 16);
        xf[s][3] = *(const uint32_t*)(base + 8 * 272 + 16);
    }

    const int gr0 = row0 + qw + g;
    #pragma unroll
    for (int m = 0; m < 2; m++) {
        const uint32_t wb = sb + 34816u * (1 + m);
        float o[16][4];
        #pragma unroll
        for (int nt = 0; nt < 16; nt++) { o[nt][0]=o[nt][1]=o[nt][2]=o[nt][3]=0.f; }
        #pragma unroll
        for (int s = 0; s < 8; s++) {
            #pragma unroll
            for (int p = 0; p < 8; p++) {
                uint32_t b0, b1, b2, b3;
                ldsm_x4_t(b0, b1, b2, b3, wb + (uint32_t)((16 * s + tr_r) * 272 + (p * 16 + tr_c) * 2));
                mma_f16(o[2 * p],     xf[s][0], xf[s][1], xf[s][2], xf[s][3], b0, b1);
                mma_f16(o[2 * p + 1], xf[s][0], xf[s][1], xf[s][2], xf[s][3], b2, b3);
            }
        }
        if (m == 0) {
            #pragma unroll
            for (int nt = 0; nt < 16; nt++) {
                *(uint32_t*)(g_Kh + (size_t)gr0 * ND + nt * 8 + 2 * t)       = pack_h2(o[nt][0], o[nt][1]);
                *(uint32_t*)(g_Kh + (size_t)(gr0 + 8) * ND + nt * 8 + 2 * t) = pack_h2(o[nt][2], o[nt][3]);
            }
        } else {
            #pragma unroll
            for (int nt = 0; nt < 16; nt++) {
                *(uint32_t*)((char*)sVst + (qw + g) * 272 + (nt * 8 + 2 * t) * 2)     = pack_h2(o[nt][0], o[nt][1]);
                *(uint32_t*)((char*)sVst + (qw + g + 8) * 272 + (nt * 8 + 2 * t) * 2) = pack_h2(o[nt][2], o[nt][3]);
            }
        }
    }
    __syncthreads();
    const int c = tid & 127, dgrp = tid >> 7;
    #pragma unroll 4
    for (int k = 0; k < 64; k++) {
        const int dd = dgrp * 64 + k;
        g_Vt[((size_t)(b * ND + dd)) * NA + a0 + c] = sVst[c * 136 + dd];
    }
}

// ======================= Kernel 2: fused Q-proj + flash attention + MLP + LN =======================
// ring: 3 stages of K(17408)+V(18432)+conn(34816) = 70656
#define STAGE_SZ 70656
#define CONN_OFF 35840
#define ATTN_SMEM (3 * STAGE_SZ)     // 211968
#define SM_QTMP  (2 * STAGE_SZ)      // prologue: x @ SM_QTMP, Wq @ SM_QTMP+34816
// epilogue: W1 @ 0, W2 @ 70656, consts @ 141312
#define MLP_CONST 141312

__device__ __forceinline__ void load_stage(uint32_t sb, int slot, int b, int q0, int k0, int tid,
                                           const float* __restrict__ conn) {
    const uint32_t base = sb + (uint32_t)(slot * STAGE_SZ);
    const __half* Kg = g_Kh + ((size_t)(b * NA + k0)) * ND;
    #pragma unroll
    for (int i = tid; i < 1024; i += 256) {
        const int r = i >> 4, c = i & 15;
        cpa16(base + (uint32_t)(r * 272 + c * 16), Kg + r * ND + c * 8);
    }
    const __half* Vg = g_Vt + ((size_t)(b * ND)) * NA + k0;
    #pragma unroll
    for (int i = tid; i < 1024; i += 256) {
        const int r = i >> 3, c = i & 7;
        cpa16(base + (uint32_t)(17408 + r * 144 + c * 16), Vg + (size_t)r * NA + c * 8);
    }
    const float* Cg = conn + ((size_t)(b * NA + q0)) * NA + k0;
    #pragma unroll
    for (int i = tid; i < 2048; i += 256) {
        const int r = i >> 4, c = i & 15;
        cpa16(base + (uint32_t)(CONN_OFF + r * 272 + c * 16), Cg + (size_t)r * NA + c * 4);
    }
}

__global__ __launch_bounds__(256, 1)
void attn_kernel(const float* __restrict__ x,
                 const float* __restrict__ conn,
                 const float* __restrict__ Wq,
                 const float* __restrict__ W1, const float* __restrict__ b1,
                 const float* __restrict__ W2, const float* __restrict__ b2,
                 const float* __restrict__ gamma, const float* __restrict__ beta,
                 float* __restrict__ out) {
    extern __shared__ __align__(16) char smem[];
    const uint32_t sb = smem_u32(smem);
    const int tid = threadIdx.x;
    const int w = tid >> 5, lane = tid & 31;
    const int g = lane >> 2, t = lane & 3;
    const int b = blockIdx.y;
    const int q0 = blockIdx.x * 128;
    const int qw = w * 16;
    const int r_l = ((lane & 16) >> 1) + (lane & 7);
    const int c_l = (lane & 8);
    const int tr_r = lane & 15, tr_c = (lane & 16) >> 1;

    // ---- kick K/V/conn prefetch for tiles 0,1 first (covers the sync Q-prologue) ----
    load_stage(sb, 0, b, q0, 0, tid, conn);
    CP_COMMIT();
    load_stage(sb, 1, b, q0, 64, tid, conn);
    CP_COMMIT();

    // ---- stage own x rows + Wq (fp32 -> fp16) into slot 2 ----
    #pragma unroll 4
    for (int it = 0; it < 16; it++) {
        const int i = tid + it * 256;
        const int r = i >> 5, c4 = (i & 31) * 4;
        const float4 v = *(const float4*)(x + (size_t)(b * NA + q0 + r) * ND + c4);
        uint2 u;
        u.x = pack_h2(v.x, v.y);
        u.y = pack_h2(v.z, v.w);
        *(uint2*)(smem + SM_QTMP + r * 272 + c4 * 2) = u;
    }
    cvt_w(smem + SM_QTMP + 34816, Wq, tid);
    __syncthreads();

    // ---- Q = x * Wq, C-frags pack straight into A-frag registers ----
    uint32_t qf[8][4];
    {
        uint32_t xf[8][4];
        #pragma unroll
        for (int s = 0; s < 8; s++) {
            const char* base = smem + SM_QTMP + (qw + g) * 272 + (16 * s + 2 * t) * 2;
            xf[s][0] = *(const uint32_t*)(base);
            xf[s][1] = *(const uint32_t*)(base + 8 * 272);
            xf[s][2] = *(const uint32_t*)(base + 16);
            xf[s][3] = *(const uint32_t*)(base + 8 * 272 + 16);
        }
        float qo[16][4];
        #pragma unroll
        for (int nt = 0; nt < 16; nt++) { qo[nt][0]=qo[nt][1]=qo[nt][2]=qo[nt][3]=0.f; }
        const uint32_t wb = sb + (uint32_t)(SM_QTMP + 34816);
        #pragma unroll
        for (int s = 0; s < 8; s++) {
            #pragma unroll
            for (int p = 0; p < 8; p++) {
                uint32_t b0, b1v, b2, b3;
                ldsm_x4_t(b0, b1v, b2, b3, wb + (uint32_t)((16 * s + tr_r) * 272 + (p * 16 + tr_c) * 2));
                mma_f16(qo[2 * p],     xf[s][0], xf[s][1], xf[s][2], xf[s][3], b0, b1v);
                mma_f16(qo[2 * p + 1], xf[s][0], xf[s][1], xf[s][2], xf[s][3], b2, b3);
            }
        }
        #pragma unroll
        for (int s = 0; s < 8; s++) {
            qf[s][0] = pack_h2(qo[2*s][0],   qo[2*s][1]);
            qf[s][1] = pack_h2(qo[2*s][2],   qo[2*s][3]);
            qf[s][2] = pack_h2(qo[2*s+1][0], qo[2*s+1][1]);
            qf[s][3] = pack_h2(qo[2*s+1][2], qo[2*s+1][3]);
        }
    }
    __syncthreads();     // slot 2 free for the ring

    float o[16][4];
    #pragma unroll
    for (int nt = 0; nt < 16; nt++) { o[nt][0]=o[nt][1]=o[nt][2]=o[nt][3]=0.f; }
    float l0 = 0.f, l1 = 0.f;

    const float K1c = 0.08838834764831845f * 1.44269504088896340f;
    const float K2c = 1.44269504088896340f;

    CP_WAIT1();          // stage0 ready
    __syncthreads();

    int slot = 0;
    for (int kt = 0; kt < 64; kt++) {
        const uint32_t stb = sb + (uint32_t)(slot * STAGE_SZ);
        const uint32_t vtb = stb + 17408u;
        if (kt) { CP_WAIT1(); __syncthreads(); }

        {
            int ps = slot + 2; if (ps >= 3) ps -= 3;
            if (kt + 2 < 64) load_stage(sb, ps, b, q0, (kt + 2) * 64, tid, conn);
            CP_COMMIT();
        }

        float sacc[8][4];
        #pragma unroll
        for (int nt = 0; nt < 8; nt++) { sacc[nt][0]=sacc[nt][1]=sacc[nt][2]=sacc[nt][3]=0.f; }

        #pragma unroll
        for (int s = 0; s < 8; s++) {
            #pragma unroll
            for (int p = 0; p < 2; p++) {
                uint32_t b0, b1v, b2, b3;
                ldsm_x4(b0, b1v, b2, b3, stb + (uint32_t)((p * 16 + r_l) * 272 + (16 * s + c_l) * 2));
                mma_f16(sacc[2 * p],     qf[s][0], qf[s][1], qf[s][2], qf[s][3], b0, b1v);
                mma_f16(sacc[2 * p + 1], qf[s][0], qf[s][1], qf[s][2], qf[s][3], b2, b3);
            }
        }
        #pragma unroll
        for (int s = 0; s < 8; s++) {
            #pragma unroll
            for (int p = 2; p < 4; p++) {
                uint32_t b0, b1v, b2, b3;
                ldsm_x4(b0, b1v, b2, b3, stb + (uint32_t)((p * 16 + r_l) * 272 + (16 * s + c_l) * 2));
                mma_f16(sacc[2 * p],     qf[s][0], qf[s][1], qf[s][2], qf[s][3], b0, b1v);
                mma_f16(sacc[2 * p + 1], qf[s][0], qf[s][1], qf[s][2], qf[s][3], b2, b3);
            }
        }

        const float* c0p = (const float*)(smem + slot * STAGE_SZ + CONN_OFF) + (qw + g) * 68 + 2 * t;
        const float* c1p = c0p + 8 * 68;

        #pragma unroll
        for (int nt = 0; nt < 4; nt++) {
            const float2 v0 = *(const float2*)(c0p + nt * 8);
            const float2 v1 = *(const float2*)(c1p + nt * 8);
            sacc[nt][0] = ex2f(fmaf(sacc[nt][0], K1c, v0.x * K2c));
            sacc[nt][1] = ex2f(fmaf(sacc[nt][1], K1c, v0.y * K2c));
            sacc[nt][2] = ex2f(fmaf(sacc[nt][2], K1c, v1.x * K2c));
            sacc[nt][3] = ex2f(fmaf(sacc[nt][3], K1c, v1.y * K2c));
            l0 += sacc[nt][0] + sacc[nt][1];
            l1 += sacc[nt][2] + sacc[nt][3];
        }
        #pragma unroll
        for (int kk = 0; kk < 2; kk++) {
            const uint32_t a0 = pack_h2(sacc[2*kk][0],   sacc[2*kk][1]);
            const uint32_t a1 = pack_h2(sacc[2*kk][2],   sacc[2*kk][3]);
            const uint32_t a2 = pack_h2(sacc[2*kk+1][0], sacc[2*kk+1][1]);
            const uint32_t a3 = pack_h2(sacc[2*kk+1][2], sacc[2*kk+1][3]);
            #pragma unroll
            for (int p = 0; p < 8; p++) {
                uint32_t b0, b1v, b2, b3;
                ldsm_x4(b0, b1v, b2, b3, vtb + (uint32_t)((p * 16 + r_l) * 144 + (16 * kk + c_l) * 2));
                mma_f16(o[2 * p],     a0, a1, a2, a3, b0, b1v);
                mma_f16(o[2 * p + 1], a0, a1, a2, a3, b2, b3);
            }
        }
        #pragma unroll
        for (int nt = 4; nt < 8; nt++) {
            const float2 v0 = *(const float2*)(c0p + nt * 8);
            const float2 v1 = *(const float2*)(c1p + nt * 8);
            sacc[nt][0] = ex2f(fmaf(sacc[nt][0], K1c, v0.x * K2c));
            sacc[nt][1] = ex2f(fmaf(sacc[nt][1], K1c, v0.y * K2c));
            sacc[nt][2] = ex2f(fmaf(sacc[nt][2], K1c, v1.x * K2c));
            sacc[nt][3] = ex2f(fmaf(sacc[nt][3], K1c, v1.y * K2c));
            l0 += sacc[nt][0] + sacc[nt][1];
            l1 += sacc[nt][2] + sacc[nt][3];
        }
        #pragma unroll
        for (int kk = 2; kk < 4; kk++) {
            const uint32_t a0 = pack_h2(sacc[2*kk][0],   sacc[2*kk][1]);
            const uint32_t a1 = pack_h2(sacc[2*kk][2],   sacc[2*kk][3]);
            const uint32_t a2 = pack_h2(sacc[2*kk+1][0], sacc[2*kk+1][1]);
            const uint32_t a3 = pack_h2(sacc[2*kk+1][2], sacc[2*kk+1][3]);
            #pragma unroll
            for (int p = 0; p < 8; p++) {
                uint32_t b0, b1v, b2, b3;
                ldsm_x4(b0, b1v, b2, b3, vtb + (uint32_t)((p * 16 + r_l) * 144 + (16 * kk + c_l) * 2));
                mma_f16(o[2 * p],     a0, a1, a2, a3, b0, b1v);
                mma_f16(o[2 * p + 1], a0, a1, a2, a3, b2, b3);
            }
        }

        slot++; if (slot >= 3) slot = 0;
    }

    // ---- l reduction + H = O/l ----
    l0 += __shfl_xor_sync(0xffffffffu, l0, 1);
    l0 += __shfl_xor_sync(0xffffffffu, l0, 2);
    l1 += __shfl_xor_sync(0xffffffffu, l1, 1);
    l1 += __shfl_xor_sync(0xffffffffu, l1, 2);
    const float r0 = 1.f / l0, r1 = 1.f / l1;

    // ---- fused MLP + LayerNorm epilogue ----
    __syncthreads();                       // everyone done with the ring
    cvt_w(smem + 0,     W1, tid);          // W1 -> slot0 area
    cvt_w(smem + 70656, W2, tid);          // W2 -> slot1 area
    {
        float* cst = (float*)(smem + MLP_CONST);
        if (tid < 128) {
            cst[tid]       = b1[tid];
            cst[128 + tid] = b2[tid];
            cst[256 + tid] = gamma[tid];
            cst[384 + tid] = beta[tid];
        }
    }
    __syncthreads();
    const float* sb1 = (const float*)(smem + MLP_CONST);
    const float* sb2 = sb1 + 128;
    const float* sgm = sb1 + 256;
    const float* sbt = sb1 + 384;

    // A-frags of swish(H) — pure register repack
    uint32_t hf[8][4];
    #pragma unroll
    for (int s = 0; s < 8; s++) {
        hf[s][0] = pack_h2(swishf(o[2*s][0] * r0),   swishf(o[2*s][1] * r0));
        hf[s][1] = pack_h2(swishf(o[2*s][2] * r1),   swishf(o[2*s][3] * r1));
        hf[s][2] = pack_h2(swishf(o[2*s+1][0] * r0), swishf(o[2*s+1][1] * r0));
        hf[s][3] = pack_h2(swishf(o[2*s+1][2] * r1), swishf(o[2*s+1][3] * r1));
    }

    // GEMM1: o1 = swish(H) * W1
    float o1[16][4];
    #pragma unroll
    for (int nt = 0; nt < 16; nt++) { o1[nt][0]=o1[nt][1]=o1[nt][2]=o1[nt][3]=0.f; }
    #pragma unroll
    for (int s = 0; s < 8; s++) {
        #pragma unroll
        for (int p = 0; p < 8; p++) {
            uint32_t b0v, b1v, b2v, b3v;
            ldsm_x4_t(b0v, b1v, b2v, b3v, sb + (uint32_t)((16 * s + tr_r) * 272 + (p * 16 + tr_c) * 2));
            mma_f16(o1[2 * p],     hf[s][0], hf[s][1], hf[s][2], hf[s][3], b0v, b1v);
            mma_f16(o1[2 * p + 1], hf[s][0], hf[s][1], hf[s][2], hf[s][3], b2v, b3v);
        }
    }
    // +b1, swish, register repack to A-frags
    uint32_t mf[8][4];
    #pragma unroll
    for (int s = 0; s < 8; s++) {
        const float2 ba = *(const float2*)(sb1 + (2*s) * 8 + 2 * t);
        const float2 bb = *(const float2*)(sb1 + (2*s+1) * 8 + 2 * t);
        mf[s][0] = pack_h2(swishf(o1[2*s][0]   + ba.x), swishf(o1[2*s][1]   + ba.y));
        mf[s][1] = pack_h2(swishf(o1[2*s][2]   + ba.x), swishf(o1[2*s][3]   + ba.y));
        mf[s][2] = pack_h2(swishf(o1[2*s+1][0] + bb.x), swishf(o1[2*s+1][1] + bb.y));
        mf[s][3] = pack_h2(swishf(o1[2*s+1][2] + bb.x), swishf(o1[2*s+1][3] + bb.y));
    }

    // GEMM2: o2 = m * W2
    float o2[16][4];
    #pragma unroll
    for (int nt = 0; nt < 16; nt++) { o2[nt][0]=o2[nt][1]=o2[nt][2]=o2[nt][3]=0.f; }
    #pragma unroll
    for (int s = 0; s < 8; s++) {
        #pragma unroll
        for (int p = 0; p < 8; p++) {
            uint32_t b0v, b1v, b2v, b3v;
            ldsm_x4_t(b0v, b1v, b2v, b3v, sb + 70656u + (uint32_t)((16 * s + tr_r) * 272 + (p * 16 + tr_c) * 2));
            mma_f16(o2[2 * p],     mf[s][0], mf[s][1], mf[s][2], mf[s][3], b0v, b1v);
            mma_f16(o2[2 * p + 1], mf[s][0], mf[s][1], mf[s][2], mf[s][3], b2v, b3v);
        }
    }
    // +b2, LayerNorm in fragments, store
    float sum0 = 0.f, sq0 = 0.f, sum1 = 0.f, sq1 = 0.f;
    #pragma unroll
    for (int nt = 0; nt < 16; nt++) {
        const float2 bb = *(const float2*)(sb2 + nt * 8 + 2 * t);
        o2[nt][0] += bb.x; o2[nt][1] += bb.y;
        o2[nt][2] += bb.x; o2[nt][3] += bb.y;
        sum0 += o2[nt][0] + o2[nt][1];
        sq0  += o2[nt][0] * o2[nt][0] + o2[nt][1] * o2[nt][1];
        sum1 += o2[nt][2] + o2[nt][3];
        sq1  += o2[nt][2] * o2[nt][2] + o2[nt][3] * o2[nt][3];
    }
    #pragma unroll
    for (int off = 1; off <= 2; off <<= 1) {
        sum0 += __shfl_xor_sync(0xffffffffu, sum0, off);
        sq0  += __shfl_xor_sync(0xffffffffu, sq0,  off);
        sum1 += __shfl_xor_sync(0xffffffffu, sum1, off);
        sq1  += __shfl_xor_sync(0xffffffffu, sq1,  off);
    }
    const float mu0 = sum0 * 0.0078125f, mu1 = sum1 * 0.0078125f;
    const float rs0 = rsqrtf(sq0 * 0.0078125f - mu0 * mu0 + 1e-5f);
    const float rs1 = rsqrtf(sq1 * 0.0078125f - mu1 * mu1 + 1e-5f);
    float* O0 = out + (size_t)(b * NA + q0 + qw + g) * ND;
    float* O1 = O0 + 8 * ND;
    #pragma unroll
    for (int nt = 0; nt < 16; nt++) {
        const float2 gm = *(const float2*)(sgm + nt * 8 + 2 * t);
        const float2 bt = *(const float2*)(sbt + nt * 8 + 2 * t);
        *(float2*)(O0 + nt * 8 + 2 * t) = make_float2(
            fmaf((o2[nt][0] - mu0) * rs0, gm.x, bt.x),
            fmaf((o2[nt][1] - mu0) * rs0, gm.y, bt.y));
        *(float2*)(O1 + nt * 8 + 2 * t) = make_float2(
            fmaf((o2[nt][2] - mu1) * rs1, gm.x, bt.x),
            fmaf((o2[nt][3] - mu1) * rs1, gm.y, bt.y));
    }
}

extern "C" void kernel_launch(void* const* d_in, const int* in_sizes, int n_in,
                              void* d_out, int out_size) {
    const float* x     = (const float*)d_in[0];
    const float* conn  = (const float*)d_in[1];
    const float* Wq    = (const float*)d_in[2];
    const float* Wk    = (const float*)d_in[3];
    const float* Wv    = (const float*)d_in[4];
    const float* W1    = (const float*)d_in[5];
    const float* b1    = (const float*)d_in[6];
    const float* W2    = (const float*)d_in[7];
    const float* b2    = (const float*)d_in[8];
    const float* gamma = (const float*)d_in[9];
    const float* beta  = (const float*)d_in[10];
    float* out = (float*)d_out;

    static bool attr_done = false;
    if (!attr_done) {
        cudaFuncSetAttribute(proj_kernel, cudaFuncAttributeMaxDynamicSharedMemorySize, PROJ_SMEM);
        cudaFuncSetAttribute(attn_kernel, cudaFuncAttributeMaxDynamicSharedMemorySize, ATTN_SMEM);
        attr_done = true;
    }

    proj_kernel<<<128, 256, PROJ_SMEM>>>(x, Wk, Wv);
    attn_kernel<<<dim3(32, 4), 256, ATTN_SMEM>>>(x, conn, Wq, W1, b1, W2, b2, gamma, beta, out);
}